// round 3
// baseline (speedup 1.0000x reference)
#include <cuda_runtime.h>

#define NMAX  1536
#define TPB   512
#define EPT   3          // strided elements per thread (NMAX / TPB)
#define NITER 20

__device__ int g_offsets[2049];
__device__ int g_maxdeg;

// ---------------------------------------------------------------------------
// Kernel 1: exclusive-scan of sizes -> g_offsets, reset g_maxdeg.
// ---------------------------------------------------------------------------
__global__ void scan_offsets_kernel(const int* __restrict__ sizes, int B) {
    __shared__ int warp_sums[32];
    int t = threadIdx.x;
    if (t == 0) g_maxdeg = 0;

    int i0 = 2 * t, i1 = 2 * t + 1;
    int s0 = (i0 < B) ? sizes[i0] : 0;
    int s1 = (i1 < B) ? sizes[i1] : 0;
    int tot = s0 + s1;

    int lane = t & 31, wid = t >> 5;
    int v = tot;
#pragma unroll
    for (int d = 1; d < 32; d <<= 1) {
        int o = __shfl_up_sync(0xffffffffu, v, d);
        if (lane >= d) v += o;
    }
    if (lane == 31) warp_sums[wid] = v;
    __syncthreads();
    if (wid == 0) {
        int w = warp_sums[lane];
#pragma unroll
        for (int d = 1; d < 32; d <<= 1) {
            int o = __shfl_up_sync(0xffffffffu, w, d);
            if (lane >= d) w += o;
        }
        warp_sums[lane] = w;
    }
    __syncthreads();
    int warp_excl = (wid > 0) ? warp_sums[wid - 1] : 0;
    int incl = v + warp_excl;
    int excl = incl - tot;
    if (i0 < B) g_offsets[i0] = excl;
    if (i1 < B) g_offsets[i1] = excl + s0;
    if (i1 == B - 1) g_offsets[B] = incl;
}

// ---------------------------------------------------------------------------
// Kernel 2: per-group degree counts -> global max degree.
// ---------------------------------------------------------------------------
__global__ void deg_kernel(const int* __restrict__ sizes,
                           const int* __restrict__ edges,
                           int N, int B) {
    __shared__ int cnt[NMAX];
    __shared__ int red[16];
    int g = blockIdx.x;
    int n = sizes[g];
    int off = g_offsets[g];
    int t = threadIdx.x;

    for (int i = t; i < n; i += blockDim.x)
        cnt[i] = (i == 0 || i == n - 1) ? 1 : 2;
    __syncthreads();

    int reBase = (N - B) + off;
    for (int i = t; i < n; i += blockDim.x) {
        int a = edges[2 * (reBase + i)]     - off;
        int b = edges[2 * (reBase + i) + 1] - off;
        atomicAdd(&cnt[a], 1);
        atomicAdd(&cnt[b], 1);
    }
    __syncthreads();

    int m = 0;
    for (int i = t; i < n; i += blockDim.x) m = max(m, cnt[i]);
#pragma unroll
    for (int d = 16; d; d >>= 1) m = max(m, __shfl_xor_sync(0xffffffffu, m, d));
    int lane = t & 31, wid = t >> 5;
    if (lane == 0) red[wid] = m;
    __syncthreads();
    if (t == 0) {
        int nw = (blockDim.x + 31) / 32;
        int mm = red[0];
        for (int w = 1; w < nw; ++w) mm = max(mm, red[w]);
        atomicMax(&g_maxdeg, mm);
    }
}

// ---------------------------------------------------------------------------
// Kernel 3: fused per-group solve. Gather-based (no atomics in iterations).
// ---------------------------------------------------------------------------
__global__ void __launch_bounds__(TPB)
main_kernel(const float* __restrict__ x,
            const int*   __restrict__ sizes,
            const int*   __restrict__ edges,
            float*       __restrict__ out,
            int N, int B) {
    __shared__ float ys[NMAX];
    __shared__ float uc[NMAX];
    __shared__ float ur[NMAX];
    __shared__ int   rowptr[NMAX + 1];
    __shared__ int   entries[2 * NMAX];
    __shared__ int   cnt[NMAX];
    __shared__ float red_s[16];
    __shared__ int   red_c[16];
    __shared__ int   warp_sc[16];
    __shared__ float s_tau;
    __shared__ int   s_cnt;

    int g   = blockIdx.x;
    int n   = sizes[g];
    int off = g_offsets[g];
    int t   = threadIdx.x;
    int reBase = (N - B) + off;
    int lane = t & 31, wid = t >> 5;

    // ---- setup: load x/edges, zero duals & counters ----
    float xr[EPT], urr[EPT], ucr[EPT];
    int   ea[EPT], eb[EPT];
    bool  act[EPT], actc[EPT];

#pragma unroll
    for (int j = 0; j < EPT; ++j) {
        int i = t + j * TPB;
        act[j]  = (i < n);
        actc[j] = (i < n - 1);
        if (act[j]) {
            xr[j] = x[off + i];
            ea[j] = edges[2 * (reBase + i)]     - off;
            eb[j] = edges[2 * (reBase + i) + 1] - off;
            uc[i] = 0.0f;
            ur[i] = 0.0f;
            cnt[i] = 0;
        } else {
            xr[j] = 0.0f; ea[j] = 0; eb[j] = 0;
        }
        urr[j] = 0.0f;
        ucr[j] = 0.0f;
    }
    float step = 0.5f / (float)g_maxdeg;
    __syncthreads();

    // count incidences
#pragma unroll
    for (int j = 0; j < EPT; ++j) {
        if (act[j]) {
            atomicAdd(&cnt[ea[j]], 1);
            atomicAdd(&cnt[eb[j]], 1);
        }
    }
    __syncthreads();

    // exclusive scan of cnt -> rowptr.  Contiguous ownership: idx = 3t..3t+2.
    {
        int c0 = 0, c1 = 0, c2 = 0;
        int ib = 3 * t;
        if (ib     < n) c0 = cnt[ib];
        if (ib + 1 < n) c1 = cnt[ib + 1];
        if (ib + 2 < n) c2 = cnt[ib + 2];
        int r0 = c0, r1 = r0 + c1, r2 = r1 + c2;
        int v = r2;
#pragma unroll
        for (int d = 1; d < 32; d <<= 1) {
            int o = __shfl_up_sync(0xffffffffu, v, d);
            if (lane >= d) v += o;
        }
        if (lane == 31) warp_sc[wid] = v;
        __syncthreads();
        if (wid == 0 && lane < 16) {
            int w = warp_sc[lane];
#pragma unroll
            for (int d = 1; d < 16; d <<= 1) {
                int o = __shfl_up_sync(0xffffu, w, d);
                if (lane >= d) w += o;
            }
            warp_sc[lane] = w;
        }
        __syncthreads();
        int base = ((wid > 0) ? warp_sc[wid - 1] : 0) + (v - r2);
        if (ib     <= n && ib     < NMAX + 1) rowptr[ib]     = base;
        if (ib + 1 <= n)                      rowptr[ib + 1] = base + r0;
        if (ib + 2 <= n)                      rowptr[ib + 2] = base + r1;
        if (ib + 3 <= n)                      rowptr[ib + 3] = base + r2;
        // reset cnt for fill
        if (ib     < n) cnt[ib]     = 0;
        if (ib + 1 < n) cnt[ib + 1] = 0;
        if (ib + 2 < n) cnt[ib + 2] = 0;
    }
    __syncthreads();

    // fill entries: (edge << 1) | sign   (sign=0 -> a endpoint, contributes -u;
    //                                     sign=1 -> b endpoint, contributes +u)
#pragma unroll
    for (int j = 0; j < EPT; ++j) {
        int i = t + j * TPB;
        if (act[j]) {
            int pa = atomicAdd(&cnt[ea[j]], 1);
            entries[rowptr[ea[j]] + pa] = (i << 1);
            int pb = atomicAdd(&cnt[eb[j]], 1);
            entries[rowptr[eb[j]] + pb] = (i << 1) | 1;
        }
    }
    __syncthreads();

    // insertion-sort each node's list (determinism of FP sum order)
    int r0c[EPT], r1c[EPT];
#pragma unroll
    for (int j = 0; j < EPT; ++j) {
        int i = t + j * TPB;
        if (act[j]) {
            int lo = rowptr[i], hi = rowptr[i + 1];
            r0c[j] = lo; r1c[j] = hi;
            for (int p = lo + 1; p < hi; ++p) {
                int key = entries[p];
                int q = p - 1;
                while (q >= lo && entries[q] > key) {
                    entries[q + 1] = entries[q];
                    --q;
                }
                entries[q + 1] = key;
            }
        } else { r0c[j] = 0; r1c[j] = 0; }
    }
    __syncthreads();

    // ---- dual-ascent iterations: 2 barriers each, no atomics ----
    float yv[EPT];
    for (int it = 0; it <= NITER; ++it) {
        // phase A: ys[i] = x[i] + uc[i-1] - uc[i] - sum(sign * ur[e])
#pragma unroll
        for (int j = 0; j < EPT; ++j) {
            int i = t + j * TPB;
            if (act[j]) {
                float v = xr[j];
                if (i > 0)   v += uc[i - 1];
                if (actc[j]) v -= ucr[j];
                for (int p = r0c[j]; p < r1c[j]; ++p) {
                    int e = entries[p];
                    float u = ur[e >> 1];
                    v += (e & 1) ? u : -u;
                }
                ys[i] = v;
                yv[j] = v;
            }
        }
        __syncthreads();
        if (it == NITER) break;
        // phase B: dual updates
#pragma unroll
        for (int j = 0; j < EPT; ++j) {
            int i = t + j * TPB;
            if (act[j]) {
                if (actc[j]) {
                    float nu = ucr[j] + step * (yv[j] - ys[i + 1]);
                    nu = fminf(1.0f, fmaxf(-1.0f, nu));
                    ucr[j] = nu;
                    uc[i] = nu;
                }
                float nu = urr[j] + step * (ys[ea[j]] - ys[eb[j]]);
                nu = fminf(1.0f, fmaxf(-1.0f, nu));
                urr[j] = nu;
                ur[i] = nu;
            }
        }
        __syncthreads();
    }

    // ---- sparsemax via Michelot (exact, no sort) ----
    // initial tau = (sum(z) - 1)/n
    {
        float s = 0.0f;
#pragma unroll
        for (int j = 0; j < EPT; ++j) if (act[j]) s += yv[j];
#pragma unroll
        for (int d = 16; d; d >>= 1) s += __shfl_xor_sync(0xffffffffu, s, d);
        if (lane == 0) red_s[wid] = s;
        __syncthreads();
        if (t == 0) {
            float ss = 0.0f;
#pragma unroll
            for (int w = 0; w < 16; ++w) ss += red_s[w];
            s_tau = (ss - 1.0f) / (float)n;
            s_cnt = n;
        }
        __syncthreads();
    }

    float tau = s_tau;
    int prev_cnt = s_cnt;

    for (int itm = 0; itm < 64; ++itm) {
        float s = 0.0f;
        int   c = 0;
#pragma unroll
        for (int j = 0; j < EPT; ++j) {
            if (act[j] && yv[j] > tau) { s += yv[j]; ++c; }
        }
#pragma unroll
        for (int d = 16; d; d >>= 1) {
            s += __shfl_xor_sync(0xffffffffu, s, d);
            c += __shfl_xor_sync(0xffffffffu, c, d);
        }
        if (lane == 0) { red_s[wid] = s; red_c[wid] = c; }
        __syncthreads();
        if (t == 0) {
            float ss = 0.0f; int cc = 0;
#pragma unroll
            for (int w = 0; w < 16; ++w) { ss += red_s[w]; cc += red_c[w]; }
            s_tau = (ss - 1.0f) / (float)cc;
            s_cnt = cc;
        }
        __syncthreads();
        tau = s_tau;
        int cnt_now = s_cnt;
        if (cnt_now == prev_cnt) break;
        prev_cnt = cnt_now;
    }

    float scale = (float)n;
#pragma unroll
    for (int j = 0; j < EPT; ++j) {
        int i = t + j * TPB;
        if (act[j]) out[off + i] = fmaxf(yv[j] - tau, 0.0f) * scale;
    }
}

// ---------------------------------------------------------------------------
extern "C" void kernel_launch(void* const* d_in, const int* in_sizes, int n_in,
                              void* d_out, int out_size) {
    const float* x     = (const float*)d_in[0];
    const int*   sizes = (const int*)  d_in[1];
    const int*   edges = (const int*)  d_in[2];
    float*       out   = (float*)d_out;
    int N = in_sizes[0];
    int B = in_sizes[1];

    scan_offsets_kernel<<<1, 1024>>>(sizes, B);
    deg_kernel<<<B, 512>>>(sizes, edges, N, B);
    main_kernel<<<B, TPB>>>(x, sizes, edges, out, N, B);
}

// round 4
// speedup vs baseline: 1.3889x; 1.3889x over previous
#include <cuda_runtime.h>

#define NMAX  1536
#define TPB   512
#define EPT   3          // strided elements per thread (NMAX / TPB)
#define NITER 20

__device__ int g_offsets[2049];
__device__ int g_maxdeg;

// ---------------------------------------------------------------------------
// Kernel 1: exclusive-scan of sizes -> g_offsets, reset g_maxdeg.
// ---------------------------------------------------------------------------
__global__ void scan_offsets_kernel(const int* __restrict__ sizes, int B) {
    __shared__ int warp_sums[32];
    int t = threadIdx.x;
    if (t == 0) g_maxdeg = 0;

    int i0 = 2 * t, i1 = 2 * t + 1;
    int s0 = (i0 < B) ? sizes[i0] : 0;
    int s1 = (i1 < B) ? sizes[i1] : 0;
    int tot = s0 + s1;

    int lane = t & 31, wid = t >> 5;
    int v = tot;
#pragma unroll
    for (int d = 1; d < 32; d <<= 1) {
        int o = __shfl_up_sync(0xffffffffu, v, d);
        if (lane >= d) v += o;
    }
    if (lane == 31) warp_sums[wid] = v;
    __syncthreads();
    if (wid == 0) {
        int w = warp_sums[lane];
#pragma unroll
        for (int d = 1; d < 32; d <<= 1) {
            int o = __shfl_up_sync(0xffffffffu, w, d);
            if (lane >= d) w += o;
        }
        warp_sums[lane] = w;
    }
    __syncthreads();
    int warp_excl = (wid > 0) ? warp_sums[wid - 1] : 0;
    int incl = v + warp_excl;
    int excl = incl - tot;
    if (i0 < B) g_offsets[i0] = excl;
    if (i1 < B) g_offsets[i1] = excl + s0;
    if (i1 == B - 1) g_offsets[B] = incl;
}

// ---------------------------------------------------------------------------
// Kernel 2: per-group degree counts -> global max degree.
// ---------------------------------------------------------------------------
__global__ void deg_kernel(const int* __restrict__ sizes,
                           const int* __restrict__ edges,
                           int N, int B) {
    __shared__ int cnt[NMAX];
    __shared__ int red[16];
    int g = blockIdx.x;
    int n = sizes[g];
    int off = g_offsets[g];
    int t = threadIdx.x;

    for (int i = t; i < n; i += blockDim.x)
        cnt[i] = (i == 0 || i == n - 1) ? 1 : 2;
    __syncthreads();

    const int2* e2 = (const int2*)edges;
    int reBase = (N - B) + off;
    for (int i = t; i < n; i += blockDim.x) {
        int2 e = e2[reBase + i];
        atomicAdd(&cnt[e.x - off], 1);
        atomicAdd(&cnt[e.y - off], 1);
    }
    __syncthreads();

    int m = 0;
    for (int i = t; i < n; i += blockDim.x) m = max(m, cnt[i]);
#pragma unroll
    for (int d = 16; d; d >>= 1) m = max(m, __shfl_xor_sync(0xffffffffu, m, d));
    int lane = t & 31, wid = t >> 5;
    if (lane == 0) red[wid] = m;
    __syncthreads();
    if (t == 0) {
        int nw = (blockDim.x + 31) / 32;
        int mm = red[0];
        for (int w = 1; w < nw; ++w) mm = max(mm, red[w]);
        atomicMax(&g_maxdeg, mm);
    }
}

// ---------------------------------------------------------------------------
// Kernel 3: fused per-group solve.
// Delta-scatter scheme, 2 barriers/iteration, chain coupling via shuffles.
// Smem: ys (y values), racc (accumulated random-edge contributions),
//       uc (chain duals, only warp-boundary slots actually used).
// ---------------------------------------------------------------------------
__global__ void __launch_bounds__(TPB)
main_kernel(const float* __restrict__ x,
            const int*   __restrict__ sizes,
            const int*   __restrict__ edges,
            float*       __restrict__ out,
            int N, int B) {
    __shared__ float ys[NMAX];
    __shared__ float racc[NMAX];
    __shared__ float uc[NMAX];
    __shared__ float red_s[16];
    __shared__ int   red_c[16];
    __shared__ float s_tau;
    __shared__ int   s_cnt;

    int g   = blockIdx.x;
    int n   = sizes[g];
    int off = g_offsets[g];
    int t   = threadIdx.x;
    int reBase = (N - B) + off;
    int lane = t & 31, wid = t >> 5;

    float xr[EPT], urr[EPT], ucr[EPT], yv[EPT];
    int   ea[EPT], eb[EPT];
    bool  act[EPT], actc[EPT];

    const int2* e2 = (const int2*)edges;
#pragma unroll
    for (int j = 0; j < EPT; ++j) {
        int i = t + j * TPB;
        act[j]  = (i < n);
        actc[j] = (i < n - 1);
        if (act[j]) {
            xr[j] = x[off + i];
            int2 e = e2[reBase + i];
            ea[j] = e.x - off;
            eb[j] = e.y - off;
            ys[i]   = xr[j];   // y0 = x (u = 0)
            racc[i] = 0.0f;
        } else {
            xr[j] = 0.0f; ea[j] = 0; eb[j] = 0;
        }
        yv[j]  = xr[j];
        urr[j] = 0.0f;
        ucr[j] = 0.0f;
    }
    float step = 0.5f / (float)g_maxdeg;
    __syncthreads();

    // ---- 20 iterations, 2 barriers each ----
    for (int it = 0; it < NITER; ++it) {
        // Phase P: dual updates from y_it (stable in ys/yv regs).
#pragma unroll
        for (int j = 0; j < EPT; ++j) {
            int i = t + j * TPB;
            float ynext = __shfl_down_sync(0xffffffffu, yv[j], 1);
            if (lane == 31 && i + 1 < NMAX) ynext = ys[i + 1];
            if (act[j]) {
                if (actc[j]) {
                    float nu = ucr[j] + step * (yv[j] - ynext);
                    ucr[j] = fminf(1.0f, fmaxf(-1.0f, nu));
                    if (lane == 31) uc[i] = ucr[j];
                }
                float ya = ys[ea[j]], yb = ys[eb[j]];
                float nu = urr[j] + step * (ya - yb);
                nu = fminf(1.0f, fmaxf(-1.0f, nu));
                float d = nu - urr[j];
                urr[j] = nu;
                atomicAdd(&racc[ea[j]], -d);
                atomicAdd(&racc[eb[j]],  d);
            }
        }
        __syncthreads();
        // Phase R: rebuild y_{it+1} = x + uc[i-1] - uc[i] + racc[i].
#pragma unroll
        for (int j = 0; j < EPT; ++j) {
            int i = t + j * TPB;
            float up = __shfl_up_sync(0xffffffffu, ucr[j], 1);
            if (lane == 0 && i > 0) up = uc[i - 1];
            if (act[j]) {
                float v = xr[j] + racc[i];
                if (i > 0)   v += up;
                if (actc[j]) v -= ucr[j];
                yv[j] = v;
                ys[i] = v;
            }
        }
        __syncthreads();
    }

    // ---- sparsemax via Michelot (exact, no sort) ----
    {
        float s = 0.0f;
#pragma unroll
        for (int j = 0; j < EPT; ++j) if (act[j]) s += yv[j];
#pragma unroll
        for (int d = 16; d; d >>= 1) s += __shfl_xor_sync(0xffffffffu, s, d);
        if (lane == 0) red_s[wid] = s;
        __syncthreads();
        if (t == 0) {
            float ss = 0.0f;
#pragma unroll
            for (int w = 0; w < 16; ++w) ss += red_s[w];
            s_tau = (ss - 1.0f) / (float)n;
            s_cnt = n;
        }
        __syncthreads();
    }

    float tau = s_tau;
    int prev_cnt = s_cnt;

    for (int itm = 0; itm < 64; ++itm) {
        float s = 0.0f;
        int   c = 0;
#pragma unroll
        for (int j = 0; j < EPT; ++j) {
            if (act[j] && yv[j] > tau) { s += yv[j]; ++c; }
        }
#pragma unroll
        for (int d = 16; d; d >>= 1) {
            s += __shfl_xor_sync(0xffffffffu, s, d);
            c += __shfl_xor_sync(0xffffffffu, c, d);
        }
        if (lane == 0) { red_s[wid] = s; red_c[wid] = c; }
        __syncthreads();
        if (t == 0) {
            float ss = 0.0f; int cc = 0;
#pragma unroll
            for (int w = 0; w < 16; ++w) { ss += red_s[w]; cc += red_c[w]; }
            s_tau = (ss - 1.0f) / (float)cc;
            s_cnt = cc;
        }
        __syncthreads();
        tau = s_tau;
        int cnt_now = s_cnt;
        if (cnt_now == prev_cnt) break;
        prev_cnt = cnt_now;
    }

    float scale = (float)n;
#pragma unroll
    for (int j = 0; j < EPT; ++j) {
        int i = t + j * TPB;
        if (act[j]) out[off + i] = fmaxf(yv[j] - tau, 0.0f) * scale;
    }
}

// ---------------------------------------------------------------------------
extern "C" void kernel_launch(void* const* d_in, const int* in_sizes, int n_in,
                              void* d_out, int out_size) {
    const float* x     = (const float*)d_in[0];
    const int*   sizes = (const int*)  d_in[1];
    const int*   edges = (const int*)  d_in[2];
    float*       out   = (float*)d_out;
    int N = in_sizes[0];
    int B = in_sizes[1];

    scan_offsets_kernel<<<1, 1024>>>(sizes, B);
    deg_kernel<<<B, 512>>>(sizes, edges, N, B);
    main_kernel<<<B, TPB>>>(x, sizes, edges, out, N, B);
}

// round 5
// speedup vs baseline: 1.3941x; 1.0038x over previous
#include <cuda_runtime.h>

#define NMAX  1536
#define TPB   128
#define EPT   12         // strided elements per thread (NMAX / TPB)
#define NSAFE 4          // elements j<NSAFE always active (n >= 512)
#define NITER 20

__device__ int g_offsets[2049];
__device__ int g_maxdeg;

// ---------------------------------------------------------------------------
// Kernel 1: exclusive-scan of sizes -> g_offsets, reset g_maxdeg.
// ---------------------------------------------------------------------------
__global__ void scan_offsets_kernel(const int* __restrict__ sizes, int B) {
    __shared__ int warp_sums[32];
    int t = threadIdx.x;
    if (t == 0) g_maxdeg = 0;

    int i0 = 2 * t, i1 = 2 * t + 1;
    int s0 = (i0 < B) ? sizes[i0] : 0;
    int s1 = (i1 < B) ? sizes[i1] : 0;
    int tot = s0 + s1;

    int lane = t & 31, wid = t >> 5;
    int v = tot;
#pragma unroll
    for (int d = 1; d < 32; d <<= 1) {
        int o = __shfl_up_sync(0xffffffffu, v, d);
        if (lane >= d) v += o;
    }
    if (lane == 31) warp_sums[wid] = v;
    __syncthreads();
    if (wid == 0) {
        int w = warp_sums[lane];
#pragma unroll
        for (int d = 1; d < 32; d <<= 1) {
            int o = __shfl_up_sync(0xffffffffu, w, d);
            if (lane >= d) w += o;
        }
        warp_sums[lane] = w;
    }
    __syncthreads();
    int warp_excl = (wid > 0) ? warp_sums[wid - 1] : 0;
    int incl = v + warp_excl;
    int excl = incl - tot;
    if (i0 < B) g_offsets[i0] = excl;
    if (i1 < B) g_offsets[i1] = excl + s0;
    if (i1 == B - 1) g_offsets[B] = incl;
}

// ---------------------------------------------------------------------------
// Kernel 2: per-group degree counts -> global max degree.
// ---------------------------------------------------------------------------
__global__ void deg_kernel(const int* __restrict__ sizes,
                           const int* __restrict__ edges,
                           int N, int B) {
    __shared__ int cnt[NMAX];
    __shared__ int red[16];
    int g = blockIdx.x;
    int n = sizes[g];
    int off = g_offsets[g];
    int t = threadIdx.x;

    for (int i = t; i < n; i += blockDim.x)
        cnt[i] = (i == 0 || i == n - 1) ? 1 : 2;
    __syncthreads();

    const int2* e2 = (const int2*)edges;
    int reBase = (N - B) + off;
    for (int i = t; i < n; i += blockDim.x) {
        int2 e = e2[reBase + i];
        atomicAdd(&cnt[e.x - off], 1);
        atomicAdd(&cnt[e.y - off], 1);
    }
    __syncthreads();

    int m = 0;
    for (int i = t; i < n; i += blockDim.x) m = max(m, cnt[i]);
#pragma unroll
    for (int d = 16; d; d >>= 1) m = max(m, __shfl_xor_sync(0xffffffffu, m, d));
    int lane = t & 31, wid = t >> 5;
    if (lane == 0) red[wid] = m;
    __syncthreads();
    if (t == 0) {
        int nw = (blockDim.x + 31) / 32;
        int mm = red[0];
        for (int w = 1; w < nw; ++w) mm = max(mm, red[w]);
        atomicMax(&g_maxdeg, mm);
    }
}

// ---------------------------------------------------------------------------
// Kernel 3: fused per-group solve. Delta-scatter, 2 barriers/iter,
// 128 threads x 12 elements for deep per-warp ILP.
// ---------------------------------------------------------------------------
__global__ void __launch_bounds__(TPB, 4)
main_kernel(const float* __restrict__ x,
            const int*   __restrict__ sizes,
            const int*   __restrict__ edges,
            float*       __restrict__ out,
            int N, int B) {
    __shared__ float ys[NMAX];
    __shared__ float racc[NMAX];
    __shared__ float uc[NMAX];
    __shared__ float red_s[4];
    __shared__ int   red_c[4];
    __shared__ float s_tau;
    __shared__ int   s_cnt;

    int g   = blockIdx.x;
    int n   = sizes[g];
    int off = g_offsets[g];
    int t   = threadIdx.x;
    int reBase = (N - B) + off;
    int lane = t & 31, wid = t >> 5;

    float xr[EPT], urr[EPT], ucr[EPT], yv[EPT];
    int   ea[EPT], eb[EPT];

    const int2* e2 = (const int2*)edges;
#pragma unroll
    for (int j = 0; j < EPT; ++j) {
        int i = t + j * TPB;
        bool a = (j < NSAFE) || (i < n);
        if (a) {
            xr[j] = x[off + i];
            int2 e = e2[reBase + i];
            ea[j] = e.x - off;
            eb[j] = e.y - off;
            ys[i]   = xr[j];
            racc[i] = 0.0f;
            uc[i]   = 0.0f;
        } else {
            xr[j] = 0.0f; ea[j] = 0; eb[j] = 0;
        }
        yv[j]  = xr[j];
        urr[j] = 0.0f;
        ucr[j] = 0.0f;
    }
    float step = 0.5f / (float)g_maxdeg;
    __syncthreads();

    // ---- 20 iterations, 2 barriers each ----
    for (int it = 0; it < NITER; ++it) {
        // Phase P: dual updates from current y (ys in smem, yv in regs).
#pragma unroll
        for (int j = 0; j < EPT; ++j) {
            int i = t + j * TPB;
            float ynext = __shfl_down_sync(0xffffffffu, yv[j], 1);
            if (lane == 31 && i + 1 < NMAX) ynext = ys[i + 1];
            bool a  = (j < NSAFE) || (i < n);
            bool ac = (i < n - 1);
            if (a) {
                if (ac) {
                    float nu = ucr[j] + step * (yv[j] - ynext);
                    ucr[j] = fminf(1.0f, fmaxf(-1.0f, nu));
                    if (lane == 31) uc[i] = ucr[j];
                }
                float ya = ys[ea[j]], yb = ys[eb[j]];
                float nu = urr[j] + step * (ya - yb);
                nu = fminf(1.0f, fmaxf(-1.0f, nu));
                float d = nu - urr[j];
                urr[j] = nu;
                atomicAdd(&racc[ea[j]], -d);
                atomicAdd(&racc[eb[j]],  d);
            }
        }
        __syncthreads();
        // Phase R: rebuild y = x + uc[i-1] - uc[i] + racc[i].
#pragma unroll
        for (int j = 0; j < EPT; ++j) {
            int i = t + j * TPB;
            float up = __shfl_up_sync(0xffffffffu, ucr[j], 1);
            if (lane == 0 && i > 0) up = uc[i - 1];
            bool a  = (j < NSAFE) || (i < n);
            bool ac = (i < n - 1);
            if (a) {
                float v = xr[j] + racc[i];
                if (i > 0) v += up;
                if (ac)    v -= ucr[j];
                yv[j] = v;
                ys[i] = v;
            }
        }
        __syncthreads();
    }

    // ---- sparsemax via Michelot (exact, no sort) ----
    {
        float s = 0.0f;
#pragma unroll
        for (int j = 0; j < EPT; ++j) {
            int i = t + j * TPB;
            if ((j < NSAFE) || (i < n)) s += yv[j];
        }
#pragma unroll
        for (int d = 16; d; d >>= 1) s += __shfl_xor_sync(0xffffffffu, s, d);
        if (lane == 0) red_s[wid] = s;
        __syncthreads();
        if (t == 0) {
            float ss = red_s[0] + red_s[1] + red_s[2] + red_s[3];
            s_tau = (ss - 1.0f) / (float)n;
            s_cnt = n;
        }
        __syncthreads();
    }

    float tau = s_tau;
    int prev_cnt = s_cnt;

    for (int itm = 0; itm < 64; ++itm) {
        float s = 0.0f;
        int   c = 0;
#pragma unroll
        for (int j = 0; j < EPT; ++j) {
            int i = t + j * TPB;
            bool a = (j < NSAFE) || (i < n);
            if (a && yv[j] > tau) { s += yv[j]; ++c; }
        }
#pragma unroll
        for (int d = 16; d; d >>= 1) {
            s += __shfl_xor_sync(0xffffffffu, s, d);
            c += __shfl_xor_sync(0xffffffffu, c, d);
        }
        if (lane == 0) { red_s[wid] = s; red_c[wid] = c; }
        __syncthreads();
        if (t == 0) {
            float ss = red_s[0] + red_s[1] + red_s[2] + red_s[3];
            int   cc = red_c[0] + red_c[1] + red_c[2] + red_c[3];
            s_tau = (ss - 1.0f) / (float)cc;
            s_cnt = cc;
        }
        __syncthreads();
        tau = s_tau;
        int cnt_now = s_cnt;
        if (cnt_now == prev_cnt) break;
        prev_cnt = cnt_now;
    }

    float scale = (float)n;
#pragma unroll
    for (int j = 0; j < EPT; ++j) {
        int i = t + j * TPB;
        if ((j < NSAFE) || (i < n))
            out[off + i] = fmaxf(yv[j] - tau, 0.0f) * scale;
    }
}

// ---------------------------------------------------------------------------
extern "C" void kernel_launch(void* const* d_in, const int* in_sizes, int n_in,
                              void* d_out, int out_size) {
    const float* x     = (const float*)d_in[0];
    const int*   sizes = (const int*)  d_in[1];
    const int*   edges = (const int*)  d_in[2];
    float*       out   = (float*)d_out;
    int N = in_sizes[0];
    int B = in_sizes[1];

    scan_offsets_kernel<<<1, 1024>>>(sizes, B);
    deg_kernel<<<B, 512>>>(sizes, edges, N, B);
    main_kernel<<<B, TPB>>>(x, sizes, edges, out, N, B);
}

// round 6
// speedup vs baseline: 1.5200x; 1.0903x over previous
#include <cuda_runtime.h>

#define NMAX  1536
#define TPB   256
#define EPT   6          // strided elements per thread (NMAX / TPB)
#define NITER 20

__device__ int g_maxdeg;

// ---------------------------------------------------------------------------
// Kernel 1 (pre): per-group offset (redundant prefix sum) + degree count
// -> global max degree via atomicMax. Also publishes nothing else; main
// recomputes its own offset the same way (cheap, deterministic).
// ---------------------------------------------------------------------------
__global__ void __launch_bounds__(512)
pre_kernel(const int* __restrict__ sizes,
           const int* __restrict__ edges,
           int N, int B) {
    __shared__ int cnt[NMAX];
    __shared__ int red[16];
    __shared__ int s_off;

    int g = blockIdx.x;
    int t = threadIdx.x;
    int lane = t & 31, wid = t >> 5;

    // offset[g] = sum of sizes[0..g)
    int part = 0;
    for (int i = t; i < g; i += 512) part += sizes[i];
#pragma unroll
    for (int d = 16; d; d >>= 1) part += __shfl_xor_sync(0xffffffffu, part, d);
    if (lane == 0) red[wid] = part;
    __syncthreads();
    if (t == 0) {
        int s = 0;
#pragma unroll
        for (int w = 0; w < 16; ++w) s += red[w];
        s_off = s;
    }
    int n = sizes[g];
    __syncthreads();
    int off = s_off;

    for (int i = t; i < n; i += 512)
        cnt[i] = (i == 0 || i == n - 1) ? 1 : 2;
    __syncthreads();

    const int2* e2 = (const int2*)edges;
    int reBase = (N - B) + off;
    for (int i = t; i < n; i += 512) {
        int2 e = e2[reBase + i];
        atomicAdd(&cnt[e.x - off], 1);
        atomicAdd(&cnt[e.y - off], 1);
    }
    __syncthreads();

    int m = 0;
    for (int i = t; i < n; i += 512) m = max(m, cnt[i]);
#pragma unroll
    for (int d = 16; d; d >>= 1) m = max(m, __shfl_xor_sync(0xffffffffu, m, d));
    if (lane == 0) red[wid] = m;
    __syncthreads();
    if (t == 0) {
        int mm = red[0];
#pragma unroll
        for (int w = 1; w < 16; ++w) mm = max(mm, red[w]);
        atomicMax(&g_maxdeg, mm);
    }
}

// ---------------------------------------------------------------------------
// Kernel 2 (main): fused per-group solve. Delta-scatter, 2 barriers/iter,
// direct-smem chain coupling, Michelot sparsemax.
// ---------------------------------------------------------------------------
__global__ void __launch_bounds__(TPB, 3)
main_kernel(const float* __restrict__ x,
            const int*   __restrict__ sizes,
            const int*   __restrict__ edges,
            float*       __restrict__ out,
            int N, int B) {
    __shared__ float ys[NMAX];
    __shared__ float racc[NMAX];
    __shared__ float uc[NMAX];
    __shared__ float red_s[8];
    __shared__ int   red_c[8];
    __shared__ int   red_i[16];
    __shared__ float s_tau;
    __shared__ int   s_cnt;
    __shared__ int   s_off;

    int g = blockIdx.x;
    int t = threadIdx.x;
    int lane = t & 31, wid = t >> 5;

    // offset[g] = sum of sizes[0..g)  (redundant recompute; L2-resident)
    {
        int part = 0;
        for (int i = t; i < g; i += TPB) part += sizes[i];
#pragma unroll
        for (int d = 16; d; d >>= 1) part += __shfl_xor_sync(0xffffffffu, part, d);
        if (lane == 0) red_i[wid] = part;
        __syncthreads();
        if (t == 0) {
            int s = 0;
#pragma unroll
            for (int w = 0; w < 8; ++w) s += red_i[w];
            s_off = s;
        }
    }
    int n = sizes[g];
    __syncthreads();
    int off = s_off;
    int reBase = (N - B) + off;

    float xr[EPT], ur[EPT], ucv[EPT], yv[EPT];
    int   ea[EPT], eb[EPT];

    const int2* e2 = (const int2*)edges;
#pragma unroll
    for (int j = 0; j < EPT; ++j) {
        int i = t + j * TPB;
        bool a = (j < 2) || (i < n);   // first 512 slots always active (n>=512)
        if (a) {
            xr[j] = x[off + i];
            int2 e = e2[reBase + i];
            ea[j] = e.x - off;
            eb[j] = e.y - off;
            ys[i]   = xr[j];
            racc[i] = 0.0f;
        } else {
            xr[j] = 0.0f; ea[j] = 0; eb[j] = 0;
        }
        yv[j]  = xr[j];
        ur[j]  = 0.0f;
        ucv[j] = 0.0f;
    }
    float step = 0.5f / (float)g_maxdeg;
    __syncthreads();

    // ---- 20 iterations, 2 barriers each ----
    for (int it = 0; it < NITER; ++it) {
        // Phase P: dual updates; chain dual to smem, random-edge delta scatter.
#pragma unroll
        for (int j = 0; j < EPT; ++j) {
            int i = t + j * TPB;
            bool a  = (j < 2) || (i < n);
            if (a) {
                bool ac = (i < n - 1);
                if (ac) {
                    float nu = ucv[j] + step * (yv[j] - ys[i + 1]);
                    nu = fminf(1.0f, fmaxf(-1.0f, nu));
                    ucv[j] = nu;
                    uc[i] = nu;
                }
                float ya = ys[ea[j]], yb = ys[eb[j]];
                float nu = ur[j] + step * (ya - yb);
                nu = fminf(1.0f, fmaxf(-1.0f, nu));
                float d = nu - ur[j];
                ur[j] = nu;
                atomicAdd(&racc[ea[j]], -d);
                atomicAdd(&racc[eb[j]],  d);
            }
        }
        __syncthreads();
        // Phase R: rebuild y = x + uc[i-1] - uc[i] + racc[i].
#pragma unroll
        for (int j = 0; j < EPT; ++j) {
            int i = t + j * TPB;
            bool a = (j < 2) || (i < n);
            if (a) {
                float v = xr[j] + racc[i];
                if (i > 0)     v += uc[i - 1];
                if (i < n - 1) v -= ucv[j];
                yv[j] = v;
                ys[i] = v;
            }
        }
        __syncthreads();
    }

    // ---- sparsemax via Michelot (exact, no sort) ----
    {
        float s = 0.0f;
#pragma unroll
        for (int j = 0; j < EPT; ++j) {
            int i = t + j * TPB;
            if ((j < 2) || (i < n)) s += yv[j];
        }
#pragma unroll
        for (int d = 16; d; d >>= 1) s += __shfl_xor_sync(0xffffffffu, s, d);
        if (lane == 0) red_s[wid] = s;
        __syncthreads();
        if (t == 0) {
            float ss = 0.0f;
#pragma unroll
            for (int w = 0; w < 8; ++w) ss += red_s[w];
            s_tau = (ss - 1.0f) / (float)n;
            s_cnt = n;
        }
        __syncthreads();
    }

    float tau = s_tau;
    int prev_cnt = s_cnt;

    for (int itm = 0; itm < 64; ++itm) {
        float s = 0.0f;
        int   c = 0;
#pragma unroll
        for (int j = 0; j < EPT; ++j) {
            int i = t + j * TPB;
            bool a = (j < 2) || (i < n);
            if (a && yv[j] > tau) { s += yv[j]; ++c; }
        }
#pragma unroll
        for (int d = 16; d; d >>= 1) {
            s += __shfl_xor_sync(0xffffffffu, s, d);
            c += __shfl_xor_sync(0xffffffffu, c, d);
        }
        if (lane == 0) { red_s[wid] = s; red_c[wid] = c; }
        __syncthreads();
        if (t == 0) {
            float ss = 0.0f; int cc = 0;
#pragma unroll
            for (int w = 0; w < 8; ++w) { ss += red_s[w]; cc += red_c[w]; }
            s_tau = (ss - 1.0f) / (float)cc;
            s_cnt = cc;
        }
        __syncthreads();
        tau = s_tau;
        int cnt_now = s_cnt;
        if (cnt_now == prev_cnt) break;
        prev_cnt = cnt_now;
    }

    float scale = (float)n;
#pragma unroll
    for (int j = 0; j < EPT; ++j) {
        int i = t + j * TPB;
        if ((j < 2) || (i < n))
            out[off + i] = fmaxf(yv[j] - tau, 0.0f) * scale;
    }
}

// ---------------------------------------------------------------------------
extern "C" void kernel_launch(void* const* d_in, const int* in_sizes, int n_in,
                              void* d_out, int out_size) {
    const float* x     = (const float*)d_in[0];
    const int*   sizes = (const int*)  d_in[1];
    const int*   edges = (const int*)  d_in[2];
    float*       out   = (float*)d_out;
    int N = in_sizes[0];
    int B = in_sizes[1];

    pre_kernel<<<B, 512>>>(sizes, edges, N, B);
    main_kernel<<<B, TPB>>>(x, sizes, edges, out, N, B);
}